// round 15
// baseline (speedup 1.0000x reference)
#include <cuda_runtime.h>
#include <math.h>

#define N_PIXELS 262144
#define N_BANDS  224
#define N_END    32
#define N_UNROLL 12

typedef unsigned long long u64;

__device__ __forceinline__ u64 pack2(float a, float b) {
    u64 r; asm("mov.b64 %0, {%1,%2};" : "=l"(r) : "f"(a), "f"(b)); return r;
}
__device__ __forceinline__ void unpack2(u64 v, float& a, float& b) {
    asm("mov.b64 {%0,%1}, %2;" : "=f"(a), "=f"(b) : "l"(v));
}
__device__ __forceinline__ u64 ffma2(u64 a, u64 b, u64 c) {
    u64 d; asm("fma.rn.f32x2 %0, %1, %2, %3;" : "=l"(d) : "l"(a), "l"(b), "l"(c)); return d;
}
__device__ __forceinline__ u64 fmul2(u64 a, u64 b) {
    u64 d; asm("mul.rn.f32x2 %0, %1, %2;" : "=l"(d) : "l"(a), "l"(b)); return d;
}
__device__ __forceinline__ u64 fadd2(u64 a, u64 b) {
    u64 d; asm("add.rn.f32x2 %0, %1, %2;" : "=l"(d) : "l"(a), "l"(b)); return d;
}
__device__ __forceinline__ u64 fsub2(u64 a, u64 b) {
    u64 d; asm("sub.rn.f32x2 %0, %1, %2;" : "=l"(d) : "l"(a), "l"(b)); return d;
}
__device__ __forceinline__ u64 neg2(u64 a) { return a ^ 0x8000000080000000ULL; }

__device__ __forceinline__ float fdiv_rn(float a, float b) {
    float r; asm("div.rn.f32 %0, %1, %2;" : "=f"(r) : "f"(a), "f"(b)); return r;
}

// Accurate expf (~1 ulp), flag-independent.
__device__ __forceinline__ float myexpf(float x) {
    x = fmaxf(x, -87.0f);
    float kf = rintf(x * 1.4426950408889634f);
    float r  = fmaf(kf, -0.693359375f, x);
    r        = fmaf(kf,  2.12194440e-4f, r);
    float p  = 1.98412698e-4f;
    p = fmaf(p, r, 1.38888889e-3f);
    p = fmaf(p, r, 8.33333333e-3f);
    p = fmaf(p, r, 4.16666667e-2f);
    p = fmaf(p, r, 1.66666667e-1f);
    p = fmaf(p, r, 0.5f);
    p = fmaf(p, r, 1.0f);
    p = fmaf(p, r, 1.0f);
    int k = (int)kf;
    float sc = __int_as_float((k + 127) << 23);
    return p * sc;
}

// TwoProd + Kahan step on packed f32x2 (lo side folded via fma).
__device__ __forceinline__ void kah_tp(u64 m2, u64 dh, u64 lo_m2, u64 dl,
                                       u64& sum, u64& comp, u64& err) {
    u64 p  = fmul2(m2, dh);
    u64 pe = ffma2(m2, dh, neg2(p));
    err = fadd2(err, pe);
    err = ffma2(lo_m2, dl, err);
    u64 y = fsub2(p, comp);
    u64 t = fadd2(sum, y);
    comp = fsub2(fsub2(t, sum), y);
    sum = t;
}

// Precomputed tables.
__device__ float g_dbar[N_BANDS];
__device__ float g_gbarHi[N_END];
__device__ float g_gbarLo[N_END];
__device__ float g_DeltaHi[N_END * N_END];
__device__ float g_DeltaLo[N_END * N_END];

__global__ void stats_kernel(const float* __restrict__ D) {
    __shared__ float Ds[N_BANDS * N_END];
    __shared__ float dbar_s[N_BANDS];
    int tid = threadIdx.x;
    for (int i = tid; i < N_BANDS * N_END / 4; i += 256)
        ((float4*)Ds)[i] = ((const float4*)D)[i];
    __syncthreads();
    if (tid < N_BANDS) {
        float ssum = 0.f;
        #pragma unroll
        for (int k = 0; k < N_END; k++) ssum += Ds[tid * 32 + k];
        float d = ssum * (1.0f / 32.0f);
        dbar_s[tid] = d;
        g_dbar[tid] = d;
    }
    __syncthreads();
    if (tid < N_END) {
        float s = 0.f, c = 0.f, er = 0.f;
        for (int b = 0; b < N_BANDS; b++) {
            float u = dbar_s[b], v = Ds[b * 32 + tid];
            float p = u * v;
            float pe = fmaf(u, v, -p);
            er += pe;
            float y = p - c;
            float t = s + y;
            c = (t - s) - y;
            s = t;
        }
        float lo = er - c;
        float hi2 = s + lo;
        float z = hi2 - s;
        float lo2 = (s - (hi2 - z)) + (lo - z);
        g_gbarHi[tid] = hi2;
        g_gbarLo[tid] = lo2;
    }
}

__global__ void delta_kernel(const float* __restrict__ D) {
    __shared__ float Ds[N_BANDS * N_END];
    int tid = threadIdx.x;
    for (int i = tid; i < N_BANDS * N_END / 4; i += 128)
        ((float4*)Ds)[i] = ((const float4*)D)[i];
    __syncthreads();
    int id = blockIdx.x * 128 + tid;
    int k = id >> 5, e = id & 31;
    float s = 0.f, c = 0.f, er = 0.f;
    for (int b = 0; b < N_BANDS; b++) {
        float u = Ds[b * 32 + k], v = Ds[b * 32 + e];
        float p = u * v;
        float pe = fmaf(u, v, -p);
        er += pe;
        float y = p - c;
        float t = s + y;
        c = (t - s) - y;
        s = t;
    }
    float lo = er - c;
    float ng = -g_gbarHi[e];
    float s1 = s + ng;
    float z1 = s1 - s;
    float e1 = (s - (s1 - z1)) + (ng - z1);
    float lo2 = (lo - g_gbarLo[e]) + e1;
    float hi3 = s1 + lo2;
    float z3 = hi3 - s1;
    float lo3 = (s1 - (hi3 - z3)) + (lo2 - z3);
    g_DeltaHi[id] = hi3;
    g_DeltaLo[id] = lo3;
}

// ---------------------------------------------------------------------------
// Main kernel: 128 threads (4 warps), one pixel/thread.
// Init softmax logits: fp32 x@D with ktile8 round-robin 2-way accumulation.
// Iterations: fully compensated (exact) centered pipeline.
// SMEM (floats):
//   Ds   [0,7168)        D [224][32]
//   Dhi  [7168,8192)     Delta hi
//   Dlo  [8192,9216)     Delta lo
//   gbh  [9216,9248)     gbar hi
//   gbl  [9248,9280)     gbar lo
//   dbar [9280,9504)
//   ets  [9504,9520)
//   xt   [9520,38448)    4 warps x (32 rows x stride 226)
//   cHI  [38448,42544)   u64[4][16][32] c-hat hi
//   cLO  [42544,46640)   u64[4][16][32] c-hat lo
__global__ __launch_bounds__(128, 1) void eda_kernel(
    const float* __restrict__ x, const float* __restrict__ D,
    const float* __restrict__ etas,
    float* __restrict__ xhat, float* __restrict__ alpha_out)
{
    extern __shared__ float s[];
    float* Ds     = s;
    float* Dhi    = s + 7168;
    float* Dlo    = s + 8192;
    float* gbh    = s + 9216;
    float* gbl    = s + 9248;
    float* dbar_s = s + 9280;
    float* ets    = s + 9504;
    float* xt     = s + 9520;
    u64*   cHI    = (u64*)(s + 38448);
    u64*   cLO    = (u64*)(s + 42544);

    const int tid = threadIdx.x;
    for (int i = tid; i < N_BANDS * N_END / 4; i += 128)
        ((float4*)Ds)[i] = ((const float4*)D)[i];
    for (int i = tid; i < 1024 / 4; i += 128) {
        ((float4*)Dhi)[i] = ((const float4*)g_DeltaHi)[i];
        ((float4*)Dlo)[i] = ((const float4*)g_DeltaLo)[i];
    }
    if (tid < N_END) { gbh[tid] = g_gbarHi[tid]; gbl[tid] = g_gbarLo[tid]; }
    for (int i = tid; i < N_BANDS; i += 128) dbar_s[i] = g_dbar[i];
    if (tid < N_UNROLL) ets[tid] = etas[tid];
    __syncthreads();

    const int warp = tid >> 5, lane = tid & 31;
    float* xw   = xt + warp * 7232;           // 32 x 226
    float* xrow = xw + lane * 226;
    const int cb = warp * 512 + lane;         // + q*32
    const int p0 = (blockIdx.x * 4 + warp) * 32;

    // ---- load x tile (coalesced, resident) ---------------------------------
    for (int t = 0; t < 7; t++) {
        #pragma unroll
        for (int r = 0; r < 32; r++)
            xw[r * 226 + t * 32 + lane] = x[(size_t)(p0 + r) * N_BANDS + t * 32 + lane];
    }
    __syncwarp();

    // ==== Phase 1a: c-hat = (x - dbar)@D, TwoProd+Kahan -> df in SMEM =======
    {
        u64 cs_[16], cc_[16], ce_[16];
        #pragma unroll
        for (int i = 0; i < 16; i++) { cs_[i] = 0ull; cc_[i] = 0ull; ce_[i] = 0ull; }
        for (int b = 0; b < N_BANDS; b++) {
            float xv = xrow[b];
            float nd = -dbar_s[b];
            float sB = xv + nd;
            float zB = sB - xv;
            float eB = (xv - (sB - zB)) + (nd - zB);
            u64 s2 = pack2(sB, sB);
            u64 e2 = pack2(eB, eB);
            const ulonglong2* dr = (const ulonglong2*)(Ds + b * 32);
            #pragma unroll
            for (int q = 0; q < 8; q++) {
                ulonglong2 dv = dr[q];
                kah_tp(s2, dv.x, e2, dv.x, cs_[2 * q],     cc_[2 * q],     ce_[2 * q]);
                kah_tp(s2, dv.y, e2, dv.y, cs_[2 * q + 1], cc_[2 * q + 1], ce_[2 * q + 1]);
            }
        }
        #pragma unroll
        for (int q = 0; q < 16; q++) {
            u64 lo = fsub2(ce_[q], cc_[q]);
            u64 hi = fadd2(cs_[q], lo);
            u64 z  = fsub2(hi, cs_[q]);
            u64 l2 = fadd2(fsub2(cs_[q], fsub2(hi, z)), fsub2(lo, z));
            cHI[cb + q * 32] = hi;
            cLO[cb + q * 32] = l2;
        }
    }

    // ==== Phase 1b: init logits = x@D fp32, ktile8 round-robin 2-WAY ========
    u64 c2[16];
    {
        u64 P[2][16];
        #pragma unroll
        for (int l = 0; l < 2; l++) {
            u64 cur[16];
            #pragma unroll
            for (int i = 0; i < 16; i++) cur[i] = 0ull;
            for (int t = l; t < 28; t += 2) {            // tiles of 8 bands
                #pragma unroll
                for (int j = 0; j < 8; j++) {
                    const int b = t * 8 + j;
                    float xv = xrow[b];
                    u64 xb2 = pack2(xv, xv);
                    const ulonglong2* dr = (const ulonglong2*)(Ds + b * 32);
                    #pragma unroll
                    for (int q = 0; q < 8; q++) {
                        ulonglong2 dv = dr[q];
                        cur[2 * q]     = ffma2(xb2, dv.x, cur[2 * q]);
                        cur[2 * q + 1] = ffma2(xb2, dv.y, cur[2 * q + 1]);
                    }
                }
            }
            #pragma unroll
            for (int i = 0; i < 16; i++) P[l][i] = cur[i];
        }
        #pragma unroll
        for (int i = 0; i < 16; i++) c2[i] = fadd2(P[0][i], P[1][i]);
    }

    // ==== Phase 2: alpha0 = softmax(fp32 logits): serial max/sum, div.rn ====
    float a[32];
    {
        float la[32];
        #pragma unroll
        for (int i = 0; i < 16; i++) unpack2(c2[i], la[2 * i], la[2 * i + 1]);
        float m = la[0];
        #pragma unroll
        for (int e = 1; e < 32; e++) m = fmaxf(m, la[e]);
        float w[32];
        #pragma unroll
        for (int e = 0; e < 32; e++) w[e] = myexpf(la[e] - m);
        float S = w[0];
        #pragma unroll
        for (int e = 1; e < 32; e++) S = S + w[e];
        #pragma unroll
        for (int e = 0; e < 32; e++) a[e] = fdiv_rn(w[e], S);
    }

    // ==== Phase 3: 12 exact-compensated iterations ===========================
    for (int it = 0; it < N_UNROLL; it++) {
        const float eta = ets[it];
        const u64 eta2 = pack2(eta, eta);

        u64 ts_[16], tc_[16], te_[16];
        #pragma unroll
        for (int i = 0; i < 16; i++) { ts_[i] = 0ull; tc_[i] = 0ull; te_[i] = 0ull; }
        #pragma unroll 4
        for (int k = 0; k < 32; k++) {
            u64 ak2 = pack2(a[k], a[k]);
            const ulonglong2* dh = (const ulonglong2*)(Dhi + k * 32);
            const ulonglong2* dl = (const ulonglong2*)(Dlo + k * 32);
            #pragma unroll
            for (int q = 0; q < 8; q++) {
                ulonglong2 hv = dh[q];
                ulonglong2 lv = dl[q];
                kah_tp(ak2, hv.x, ak2, lv.x, ts_[2 * q],     tc_[2 * q],     te_[2 * q]);
                kah_tp(ak2, hv.y, ak2, lv.y, ts_[2 * q + 1], tc_[2 * q + 1], te_[2 * q + 1]);
            }
        }

        // b = eta * (c-hat - t), df
        float bhf[32], blf[32];
        #pragma unroll
        for (int q = 0; q < 16; q++) {
            u64 ch = cHI[cb + q * 32];
            u64 cl = cLO[cb + q * 32];
            u64 tc2 = fsub2(te_[q], tc_[q]);
            u64 nts = neg2(ts_[q]);
            u64 b1 = fadd2(ch, nts);
            u64 z  = fsub2(b1, ch);
            u64 e1 = fadd2(fsub2(ch, fsub2(b1, z)), fsub2(nts, z));
            u64 blo = fadd2(fsub2(cl, tc2), e1);
            u64 h = fmul2(eta2, b1);
            u64 l = ffma2(eta2, b1, neg2(h));
            l = ffma2(eta2, blo, l);
            unpack2(h, bhf[2 * q], bhf[2 * q + 1]);
            unpack2(l, blf[2 * q], blf[2 * q + 1]);
        }

        float m = bhf[0];
        #pragma unroll
        for (int e = 1; e < 32; e++) m = fmaxf(m, bhf[e]);
        float S = 0.f;
        float w[32];
        #pragma unroll
        for (int e = 0; e < 32; e++) {
            float nm = -m;
            float s1 = bhf[e] + nm;
            float z1 = s1 - bhf[e];
            float e1 = (bhf[e] - (s1 - z1)) + (nm - z1);
            float al = e1 + blf[e];
            float E  = myexpf(s1);
            E = fmaf(E, al, E);
            float wv = a[e] * E;
            w[e] = wv;
            S = S + wv;
        }
        #pragma unroll
        for (int e = 0; e < 32; e++) a[e] = fdiv_rn(w[e], S);
    }

    // ==== Phase 4: outputs ====================================================
    #pragma unroll
    for (int e = 0; e < 32; e++) xrow[e] = a[e];
    __syncwarp();
    #pragma unroll
    for (int r = 0; r < 32; r++)
        alpha_out[(size_t)(p0 + r) * N_END + lane] = xw[r * 226 + lane];
    __syncwarp();

    {
        u64 ap2[16];
        #pragma unroll
        for (int i = 0; i < 16; i++) ap2[i] = pack2(a[2 * i], a[2 * i + 1]);
        for (int t = 0; t < 7; t++) {
            #pragma unroll 4
            for (int bb = 0; bb < 32; bb++) {
                const int b = t * 32 + bb;
                const ulonglong2* dr = (const ulonglong2*)(Ds + b * 32);
                u64 ac0 = 0ull, ac1 = 0ull;
                #pragma unroll
                for (int q = 0; q < 8; q++) {
                    ulonglong2 dv = dr[q];
                    ac0 = ffma2(ap2[2 * q],     dv.x, ac0);
                    ac1 = ffma2(ap2[2 * q + 1], dv.y, ac1);
                }
                u64 ss = fadd2(ac0, ac1);
                float h0, h1; unpack2(ss, h0, h1);
                xw[lane * 226 + bb] = h0 + h1;
            }
            __syncwarp();
            #pragma unroll
            for (int r = 0; r < 32; r++)
                xhat[(size_t)(p0 + r) * N_BANDS + t * 32 + lane] = xw[r * 226 + lane];
            __syncwarp();
        }
    }
}

extern "C" void kernel_launch(void* const* d_in, const int* in_sizes, int n_in,
                              void* d_out, int out_size) {
    const float* x    = (const float*)d_in[0];
    const float* D    = (const float*)d_in[1];
    const float* etas = (const float*)d_in[2];
    float* out   = (float*)d_out;
    float* xhat  = out;                                   // [N, 224]
    float* alpha = out + (size_t)N_PIXELS * N_BANDS;      // [N, 32]

    stats_kernel<<<1, 256>>>(D);
    delta_kernel<<<8, 128>>>(D);

    const int smem_bytes = 46640 * 4;                     // 186,560 B
    cudaFuncSetAttribute(eda_kernel,
                         cudaFuncAttributeMaxDynamicSharedMemorySize, smem_bytes);
    eda_kernel<<<N_PIXELS / 128, 128, smem_bytes>>>(x, D, etas, xhat, alpha);
}

// round 16
// speedup vs baseline: 1.4189x; 1.4189x over previous
#include <cuda_runtime.h>
#include <math.h>

#define N_PIXELS 262144
#define N_BANDS  224
#define N_END    32
#define N_UNROLL 12

typedef unsigned long long u64;

__device__ __forceinline__ u64 pack2(float a, float b) {
    u64 r; asm("mov.b64 %0, {%1,%2};" : "=l"(r) : "f"(a), "f"(b)); return r;
}
__device__ __forceinline__ void unpack2(u64 v, float& a, float& b) {
    asm("mov.b64 {%0,%1}, %2;" : "=f"(a), "=f"(b) : "l"(v));
}
__device__ __forceinline__ u64 ffma2(u64 a, u64 b, u64 c) {
    u64 d; asm("fma.rn.f32x2 %0, %1, %2, %3;" : "=l"(d) : "l"(a), "l"(b), "l"(c)); return d;
}
__device__ __forceinline__ u64 fmul2(u64 a, u64 b) {
    u64 d; asm("mul.rn.f32x2 %0, %1, %2;" : "=l"(d) : "l"(a), "l"(b)); return d;
}
__device__ __forceinline__ u64 fadd2(u64 a, u64 b) {
    u64 d; asm("add.rn.f32x2 %0, %1, %2;" : "=l"(d) : "l"(a), "l"(b)); return d;
}
__device__ __forceinline__ u64 fsub2(u64 a, u64 b) {
    u64 d; asm("sub.rn.f32x2 %0, %1, %2;" : "=l"(d) : "l"(a), "l"(b)); return d;
}
__device__ __forceinline__ u64 neg2(u64 a) { return a ^ 0x8000000080000000ULL; }

__device__ __forceinline__ float fdiv_rn(float a, float b) {
    float r; asm("div.rn.f32 %0, %1, %2;" : "=f"(r) : "f"(a), "f"(b)); return r;
}

// Accurate expf (~1 ulp), flag-independent.
__device__ __forceinline__ float myexpf(float x) {
    x = fmaxf(x, -87.0f);
    float kf = rintf(x * 1.4426950408889634f);
    float r  = fmaf(kf, -0.693359375f, x);
    r        = fmaf(kf,  2.12194440e-4f, r);
    float p  = 1.98412698e-4f;
    p = fmaf(p, r, 1.38888889e-3f);
    p = fmaf(p, r, 8.33333333e-3f);
    p = fmaf(p, r, 4.16666667e-2f);
    p = fmaf(p, r, 1.66666667e-1f);
    p = fmaf(p, r, 0.5f);
    p = fmaf(p, r, 1.0f);
    p = fmaf(p, r, 1.0f);
    int k = (int)kf;
    float sc = __int_as_float((k + 127) << 23);
    return p * sc;
}

// TwoProd + Kahan step on packed f32x2 (lo side folded via fma).
__device__ __forceinline__ void kah_tp(u64 m2, u64 dh, u64 lo_m2, u64 dl,
                                       u64& sum, u64& comp, u64& err) {
    u64 p  = fmul2(m2, dh);
    u64 pe = ffma2(m2, dh, neg2(p));
    err = fadd2(err, pe);
    err = ffma2(lo_m2, dl, err);
    u64 y = fsub2(p, comp);
    u64 t = fadd2(sum, y);
    comp = fsub2(fsub2(t, sum), y);
    sum = t;
}

// Precomputed tables.
__device__ float g_dbar[N_BANDS];
__device__ float g_gbarHi[N_END];
__device__ float g_gbarLo[N_END];
__device__ float g_DeltaHi[N_END * N_END];
__device__ float g_DeltaLo[N_END * N_END];

__global__ void stats_kernel(const float* __restrict__ D) {
    __shared__ float Ds[N_BANDS * N_END];
    __shared__ float dbar_s[N_BANDS];
    int tid = threadIdx.x;
    for (int i = tid; i < N_BANDS * N_END / 4; i += 256)
        ((float4*)Ds)[i] = ((const float4*)D)[i];
    __syncthreads();
    if (tid < N_BANDS) {
        float ssum = 0.f;
        #pragma unroll
        for (int k = 0; k < N_END; k++) ssum += Ds[tid * 32 + k];
        float d = ssum * (1.0f / 32.0f);
        dbar_s[tid] = d;
        g_dbar[tid] = d;
    }
    __syncthreads();
    if (tid < N_END) {
        float s = 0.f, c = 0.f, er = 0.f;
        for (int b = 0; b < N_BANDS; b++) {
            float u = dbar_s[b], v = Ds[b * 32 + tid];
            float p = u * v;
            float pe = fmaf(u, v, -p);
            er += pe;
            float y = p - c;
            float t = s + y;
            c = (t - s) - y;
            s = t;
        }
        float lo = er - c;
        float hi2 = s + lo;
        float z = hi2 - s;
        float lo2 = (s - (hi2 - z)) + (lo - z);
        g_gbarHi[tid] = hi2;
        g_gbarLo[tid] = lo2;
    }
}

__global__ void delta_kernel(const float* __restrict__ D) {
    __shared__ float Ds[N_BANDS * N_END];
    int tid = threadIdx.x;
    for (int i = tid; i < N_BANDS * N_END / 4; i += 128)
        ((float4*)Ds)[i] = ((const float4*)D)[i];
    __syncthreads();
    int id = blockIdx.x * 128 + tid;
    int k = id >> 5, e = id & 31;
    float s = 0.f, c = 0.f, er = 0.f;
    for (int b = 0; b < N_BANDS; b++) {
        float u = Ds[b * 32 + k], v = Ds[b * 32 + e];
        float p = u * v;
        float pe = fmaf(u, v, -p);
        er += pe;
        float y = p - c;
        float t = s + y;
        c = (t - s) - y;
        s = t;
    }
    float lo = er - c;
    float ng = -g_gbarHi[e];
    float s1 = s + ng;
    float z1 = s1 - s;
    float e1 = (s - (s1 - z1)) + (ng - z1);
    float lo2 = (lo - g_gbarLo[e]) + e1;
    float hi3 = s1 + lo2;
    float z3 = hi3 - s1;
    float lo3 = (s1 - (hi3 - z3)) + (lo2 - z3);
    g_DeltaHi[id] = hi3;
    g_DeltaLo[id] = lo3;
}

// ---------------------------------------------------------------------------
// Main kernel: 256 threads (8 warps), one pixel/thread. x staged per 32-band
// tile (not resident) -> smem 203KB -> 8 warps/SM (2 per SMSP).
// Arithmetic is bitwise identical to the R15 passing kernel.
// SMEM (floats):
//   Ds    [0,7168)       D [224][32]
//   Dhi   [7168,8192)    Delta hi
//   Dlo   [8192,9216)    Delta lo
//   gbh   [9216,9248)    gbar hi
//   gbl   [9248,9280)    gbar lo
//   dbar  [9280,9504)
//   ets   [9504,9520)
//   stage [9520,17968)   8 warps x (32 rows x stride 33)
//   cHI   [17968,34352)  u64[8][16][32] c-hat hi
//   cLO   [34352,50736)  u64[8][16][32] c-hat lo
__global__ __launch_bounds__(256, 1) void eda_kernel(
    const float* __restrict__ x, const float* __restrict__ D,
    const float* __restrict__ etas,
    float* __restrict__ xhat, float* __restrict__ alpha_out)
{
    extern __shared__ float s[];
    float* Ds     = s;
    float* Dhi    = s + 7168;
    float* Dlo    = s + 8192;
    float* gbh    = s + 9216;
    float* gbl    = s + 9248;
    float* dbar_s = s + 9280;
    float* ets    = s + 9504;
    float* stage  = s + 9520;
    u64*   cHI    = (u64*)(s + 17968);
    u64*   cLO    = (u64*)(s + 34352);

    const int tid = threadIdx.x;
    for (int i = tid; i < N_BANDS * N_END / 4; i += 256)
        ((float4*)Ds)[i] = ((const float4*)D)[i];
    for (int i = tid; i < 1024 / 4; i += 256) {
        ((float4*)Dhi)[i] = ((const float4*)g_DeltaHi)[i];
        ((float4*)Dlo)[i] = ((const float4*)g_DeltaLo)[i];
    }
    if (tid < N_END) { gbh[tid] = g_gbarHi[tid]; gbl[tid] = g_gbarLo[tid]; }
    if (tid < N_BANDS) dbar_s[tid] = g_dbar[tid];
    if (tid < N_UNROLL) ets[tid] = etas[tid];
    __syncthreads();

    const int warp = tid >> 5, lane = tid & 31;
    float* xw = stage + warp * 1056;          // 32 x 33
    const int cb = warp * 512 + lane;         // + q*32
    const int p0 = (blockIdx.x * 8 + warp) * 32;

    // ==== Pass A: init logits = x@D fp32, ktile8 round-robin 2-WAY ==========
    // (Global ktile order into each accumulator matches R15: P0 gets 0,2,4,...
    //  P1 gets 1,3,5,...; within-ktile bands ascending.)
    u64 c2[16];
    {
        u64 P0[16], P1[16];
        #pragma unroll
        for (int i = 0; i < 16; i++) { P0[i] = 0ull; P1[i] = 0ull; }
        for (int t = 0; t < 7; t++) {
            #pragma unroll
            for (int r = 0; r < 32; r++)
                xw[r * 33 + lane] = x[(size_t)(p0 + r) * N_BANDS + t * 32 + lane];
            __syncwarp();
            #pragma unroll
            for (int st = 0; st < 4; st++) {       // global ktile = 4t+st
                u64* P = (st & 1) ? P1 : P0;
                #pragma unroll
                for (int j = 0; j < 8; j++) {
                    const int bb = st * 8 + j;
                    const int b  = t * 32 + bb;
                    float xv = xw[lane * 33 + bb];
                    u64 xb2 = pack2(xv, xv);
                    const ulonglong2* dr = (const ulonglong2*)(Ds + b * 32);
                    #pragma unroll
                    for (int q = 0; q < 8; q++) {
                        ulonglong2 dv = dr[q];
                        P[2 * q]     = ffma2(xb2, dv.x, P[2 * q]);
                        P[2 * q + 1] = ffma2(xb2, dv.y, P[2 * q + 1]);
                    }
                }
            }
            __syncwarp();
        }
        #pragma unroll
        for (int i = 0; i < 16; i++) c2[i] = fadd2(P0[i], P1[i]);
    }

    // ==== alpha0 = softmax(fp32 logits): serial max/sum, div.rn =============
    float a[32];
    {
        float la[32];
        #pragma unroll
        for (int i = 0; i < 16; i++) unpack2(c2[i], la[2 * i], la[2 * i + 1]);
        float m = la[0];
        #pragma unroll
        for (int e = 1; e < 32; e++) m = fmaxf(m, la[e]);
        float w[32];
        #pragma unroll
        for (int e = 0; e < 32; e++) w[e] = myexpf(la[e] - m);
        float S = w[0];
        #pragma unroll
        for (int e = 1; e < 32; e++) S = S + w[e];
        #pragma unroll
        for (int e = 0; e < 32; e++) a[e] = fdiv_rn(w[e], S);
    }

    // ==== Pass B: c-hat = (x - dbar)@D, TwoProd+Kahan -> df in SMEM =========
    {
        u64 cs_[16], cc_[16], ce_[16];
        #pragma unroll
        for (int i = 0; i < 16; i++) { cs_[i] = 0ull; cc_[i] = 0ull; ce_[i] = 0ull; }
        for (int t = 0; t < 7; t++) {
            #pragma unroll
            for (int r = 0; r < 32; r++)
                xw[r * 33 + lane] = x[(size_t)(p0 + r) * N_BANDS + t * 32 + lane];
            __syncwarp();
            #pragma unroll 4
            for (int bb = 0; bb < 32; bb++) {
                const int b = t * 32 + bb;
                float xv = xw[lane * 33 + bb];
                float nd = -dbar_s[b];
                float sB = xv + nd;
                float zB = sB - xv;
                float eB = (xv - (sB - zB)) + (nd - zB);
                u64 s2 = pack2(sB, sB);
                u64 e2 = pack2(eB, eB);
                const ulonglong2* dr = (const ulonglong2*)(Ds + b * 32);
                #pragma unroll
                for (int q = 0; q < 8; q++) {
                    ulonglong2 dv = dr[q];
                    kah_tp(s2, dv.x, e2, dv.x, cs_[2 * q],     cc_[2 * q],     ce_[2 * q]);
                    kah_tp(s2, dv.y, e2, dv.y, cs_[2 * q + 1], cc_[2 * q + 1], ce_[2 * q + 1]);
                }
            }
            __syncwarp();
        }
        #pragma unroll
        for (int q = 0; q < 16; q++) {
            u64 lo = fsub2(ce_[q], cc_[q]);
            u64 hi = fadd2(cs_[q], lo);
            u64 z  = fsub2(hi, cs_[q]);
            u64 l2 = fadd2(fsub2(cs_[q], fsub2(hi, z)), fsub2(lo, z));
            cHI[cb + q * 32] = hi;
            cLO[cb + q * 32] = l2;
        }
    }

    // ==== 12 exact-compensated iterations ====================================
    for (int it = 0; it < N_UNROLL; it++) {
        const float eta = ets[it];
        const u64 eta2 = pack2(eta, eta);

        u64 ts_[16], tc_[16], te_[16];
        #pragma unroll
        for (int i = 0; i < 16; i++) { ts_[i] = 0ull; tc_[i] = 0ull; te_[i] = 0ull; }
        #pragma unroll 4
        for (int k = 0; k < 32; k++) {
            u64 ak2 = pack2(a[k], a[k]);
            const ulonglong2* dh = (const ulonglong2*)(Dhi + k * 32);
            const ulonglong2* dl = (const ulonglong2*)(Dlo + k * 32);
            #pragma unroll
            for (int q = 0; q < 8; q++) {
                ulonglong2 hv = dh[q];
                ulonglong2 lv = dl[q];
                kah_tp(ak2, hv.x, ak2, lv.x, ts_[2 * q],     tc_[2 * q],     te_[2 * q]);
                kah_tp(ak2, hv.y, ak2, lv.y, ts_[2 * q + 1], tc_[2 * q + 1], te_[2 * q + 1]);
            }
        }

        // b = eta * (c-hat - t), df
        float bhf[32], blf[32];
        #pragma unroll
        for (int q = 0; q < 16; q++) {
            u64 ch = cHI[cb + q * 32];
            u64 cl = cLO[cb + q * 32];
            u64 tc2 = fsub2(te_[q], tc_[q]);
            u64 nts = neg2(ts_[q]);
            u64 b1 = fadd2(ch, nts);
            u64 z  = fsub2(b1, ch);
            u64 e1 = fadd2(fsub2(ch, fsub2(b1, z)), fsub2(nts, z));
            u64 blo = fadd2(fsub2(cl, tc2), e1);
            u64 h = fmul2(eta2, b1);
            u64 l = ffma2(eta2, b1, neg2(h));
            l = ffma2(eta2, blo, l);
            unpack2(h, bhf[2 * q], bhf[2 * q + 1]);
            unpack2(l, blf[2 * q], blf[2 * q + 1]);
        }

        float m = bhf[0];
        #pragma unroll
        for (int e = 1; e < 32; e++) m = fmaxf(m, bhf[e]);
        float S = 0.f;
        float w[32];
        #pragma unroll
        for (int e = 0; e < 32; e++) {
            float nm = -m;
            float s1 = bhf[e] + nm;
            float z1 = s1 - bhf[e];
            float e1 = (bhf[e] - (s1 - z1)) + (nm - z1);
            float al = e1 + blf[e];
            float E  = myexpf(s1);
            E = fmaf(E, al, E);
            float wv = a[e] * E;
            w[e] = wv;
            S = S + wv;
        }
        #pragma unroll
        for (int e = 0; e < 32; e++) a[e] = fdiv_rn(w[e], S);
    }

    // ==== outputs =============================================================
    #pragma unroll
    for (int e = 0; e < 32; e++) xw[lane * 33 + e] = a[e];
    __syncwarp();
    #pragma unroll
    for (int r = 0; r < 32; r++)
        alpha_out[(size_t)(p0 + r) * N_END + lane] = xw[r * 33 + lane];
    __syncwarp();

    {
        u64 ap2[16];
        #pragma unroll
        for (int i = 0; i < 16; i++) ap2[i] = pack2(a[2 * i], a[2 * i + 1]);
        for (int t = 0; t < 7; t++) {
            #pragma unroll 4
            for (int bb = 0; bb < 32; bb++) {
                const int b = t * 32 + bb;
                const ulonglong2* dr = (const ulonglong2*)(Ds + b * 32);
                u64 ac0 = 0ull, ac1 = 0ull;
                #pragma unroll
                for (int q = 0; q < 8; q++) {
                    ulonglong2 dv = dr[q];
                    ac0 = ffma2(ap2[2 * q],     dv.x, ac0);
                    ac1 = ffma2(ap2[2 * q + 1], dv.y, ac1);
                }
                u64 ss = fadd2(ac0, ac1);
                float h0, h1; unpack2(ss, h0, h1);
                xw[lane * 33 + bb] = h0 + h1;
            }
            __syncwarp();
            #pragma unroll
            for (int r = 0; r < 32; r++)
                xhat[(size_t)(p0 + r) * N_BANDS + t * 32 + lane] = xw[r * 33 + lane];
            __syncwarp();
        }
    }
}

extern "C" void kernel_launch(void* const* d_in, const int* in_sizes, int n_in,
                              void* d_out, int out_size) {
    const float* x    = (const float*)d_in[0];
    const float* D    = (const float*)d_in[1];
    const float* etas = (const float*)d_in[2];
    float* out   = (float*)d_out;
    float* xhat  = out;                                   // [N, 224]
    float* alpha = out + (size_t)N_PIXELS * N_BANDS;      // [N, 32]

    stats_kernel<<<1, 256>>>(D);
    delta_kernel<<<8, 128>>>(D);

    const int smem_bytes = 50736 * 4;                     // 202,944 B
    cudaFuncSetAttribute(eda_kernel,
                         cudaFuncAttributeMaxDynamicSharedMemorySize, smem_bytes);
    eda_kernel<<<N_PIXELS / 256, 256, smem_bytes>>>(x, D, etas, xhat, alpha);
}

// round 17
// speedup vs baseline: 2.3021x; 1.6224x over previous
#include <cuda_runtime.h>
#include <math.h>

#define N_PIXELS 262144
#define N_BANDS  224
#define N_END    32
#define N_UNROLL 12

typedef unsigned long long u64;

__device__ __forceinline__ u64 pack2(float a, float b) {
    u64 r; asm("mov.b64 %0, {%1,%2};" : "=l"(r) : "f"(a), "f"(b)); return r;
}
__device__ __forceinline__ void unpack2(u64 v, float& a, float& b) {
    asm("mov.b64 {%0,%1}, %2;" : "=f"(a), "=f"(b) : "l"(v));
}
__device__ __forceinline__ u64 ffma2(u64 a, u64 b, u64 c) {
    u64 d; asm("fma.rn.f32x2 %0, %1, %2, %3;" : "=l"(d) : "l"(a), "l"(b), "l"(c)); return d;
}
__device__ __forceinline__ u64 fmul2(u64 a, u64 b) {
    u64 d; asm("mul.rn.f32x2 %0, %1, %2;" : "=l"(d) : "l"(a), "l"(b)); return d;
}
__device__ __forceinline__ u64 fadd2(u64 a, u64 b) {
    u64 d; asm("add.rn.f32x2 %0, %1, %2;" : "=l"(d) : "l"(a), "l"(b)); return d;
}
__device__ __forceinline__ u64 fsub2(u64 a, u64 b) {
    u64 d; asm("sub.rn.f32x2 %0, %1, %2;" : "=l"(d) : "l"(a), "l"(b)); return d;
}
__device__ __forceinline__ u64 neg2(u64 a) { return a ^ 0x8000000080000000ULL; }

__device__ __forceinline__ float fdiv_rn(float a, float b) {
    float r; asm("div.rn.f32 %0, %1, %2;" : "=f"(r) : "f"(a), "f"(b)); return r;
}

// Accurate expf (~1 ulp), flag-independent.
__device__ __forceinline__ float myexpf(float x) {
    x = fmaxf(x, -87.0f);
    float kf = rintf(x * 1.4426950408889634f);
    float r  = fmaf(kf, -0.693359375f, x);
    r        = fmaf(kf,  2.12194440e-4f, r);
    float p  = 1.98412698e-4f;
    p = fmaf(p, r, 1.38888889e-3f);
    p = fmaf(p, r, 8.33333333e-3f);
    p = fmaf(p, r, 4.16666667e-2f);
    p = fmaf(p, r, 1.66666667e-1f);
    p = fmaf(p, r, 0.5f);
    p = fmaf(p, r, 1.0f);
    p = fmaf(p, r, 1.0f);
    int k = (int)kf;
    float sc = __int_as_float((k + 127) << 23);
    return p * sc;
}

// TwoProd + Kahan step on packed f32x2 (lo side folded via fma).
__device__ __forceinline__ void kah_tp(u64 m2, u64 dh, u64 lo_m2, u64 dl,
                                       u64& sum, u64& comp, u64& err) {
    u64 p  = fmul2(m2, dh);
    u64 pe = ffma2(m2, dh, neg2(p));
    err = fadd2(err, pe);
    err = ffma2(lo_m2, dl, err);
    u64 y = fsub2(p, comp);
    u64 t = fadd2(sum, y);
    comp = fsub2(fsub2(t, sum), y);
    sum = t;
}

// Precomputed tables.
__device__ float g_dbar[N_BANDS];
__device__ float g_gbarHi[N_END];
__device__ float g_gbarLo[N_END];
__device__ float g_DeltaHi[N_END * N_END];
__device__ float g_DeltaLo[N_END * N_END];

__global__ void stats_kernel(const float* __restrict__ D) {
    __shared__ float Ds[N_BANDS * N_END];
    __shared__ float dbar_s[N_BANDS];
    int tid = threadIdx.x;
    for (int i = tid; i < N_BANDS * N_END / 4; i += 256)
        ((float4*)Ds)[i] = ((const float4*)D)[i];
    __syncthreads();
    if (tid < N_BANDS) {
        float ssum = 0.f;
        #pragma unroll
        for (int k = 0; k < N_END; k++) ssum += Ds[tid * 32 + k];
        float d = ssum * (1.0f / 32.0f);
        dbar_s[tid] = d;
        g_dbar[tid] = d;
    }
    __syncthreads();
    if (tid < N_END) {
        float s = 0.f, c = 0.f, er = 0.f;
        for (int b = 0; b < N_BANDS; b++) {
            float u = dbar_s[b], v = Ds[b * 32 + tid];
            float p = u * v;
            float pe = fmaf(u, v, -p);
            er += pe;
            float y = p - c;
            float t = s + y;
            c = (t - s) - y;
            s = t;
        }
        float lo = er - c;
        float hi2 = s + lo;
        float z = hi2 - s;
        float lo2 = (s - (hi2 - z)) + (lo - z);
        g_gbarHi[tid] = hi2;
        g_gbarLo[tid] = lo2;
    }
}

__global__ void delta_kernel(const float* __restrict__ D) {
    __shared__ float Ds[N_BANDS * N_END];
    int tid = threadIdx.x;
    for (int i = tid; i < N_BANDS * N_END / 4; i += 128)
        ((float4*)Ds)[i] = ((const float4*)D)[i];
    __syncthreads();
    int id = blockIdx.x * 128 + tid;
    int k = id >> 5, e = id & 31;
    float s = 0.f, c = 0.f, er = 0.f;
    for (int b = 0; b < N_BANDS; b++) {
        float u = Ds[b * 32 + k], v = Ds[b * 32 + e];
        float p = u * v;
        float pe = fmaf(u, v, -p);
        er += pe;
        float y = p - c;
        float t = s + y;
        c = (t - s) - y;
        s = t;
    }
    float lo = er - c;
    float ng = -g_gbarHi[e];
    float s1 = s + ng;
    float z1 = s1 - s;
    float e1 = (s - (s1 - z1)) + (ng - z1);
    float lo2 = (lo - g_gbarLo[e]) + e1;
    float hi3 = s1 + lo2;
    float z3 = hi3 - s1;
    float lo3 = (s1 - (hi3 - z3)) + (lo2 - z3);
    g_DeltaHi[id] = hi3;
    g_DeltaLo[id] = lo3;
}

// ---------------------------------------------------------------------------
// Main kernel: 256 threads (8 warps), one pixel/thread. x staged per 32-band
// tile; iterations use PLAIN dual (hi,lo) FFMA matvecs (R3-validated noise
// level); init logits ktile8-RR-2way fp32; c-hat Kahan df (frozen term).
// SMEM (floats):
//   Ds    [0,7168)       D [224][32]
//   Dhi   [7168,8192)    Delta hi
//   Dlo   [8192,9216)    Delta lo
//   gbh   [9216,9248)    gbar hi
//   gbl   [9248,9280)    gbar lo
//   dbar  [9280,9504)
//   ets   [9504,9520)
//   stage [9520,17968)   8 warps x (32 rows x stride 33)
//   cHI   [17968,34352)  u64[8][16][32] c-hat hi
//   cLO   [34352,50736)  u64[8][16][32] c-hat lo
__global__ __launch_bounds__(256, 1) void eda_kernel(
    const float* __restrict__ x, const float* __restrict__ D,
    const float* __restrict__ etas,
    float* __restrict__ xhat, float* __restrict__ alpha_out)
{
    extern __shared__ float s[];
    float* Ds     = s;
    float* Dhi    = s + 7168;
    float* Dlo    = s + 8192;
    float* gbh    = s + 9216;
    float* gbl    = s + 9248;
    float* dbar_s = s + 9280;
    float* ets    = s + 9504;
    float* stage  = s + 9520;
    u64*   cHI    = (u64*)(s + 17968);
    u64*   cLO    = (u64*)(s + 34352);

    const int tid = threadIdx.x;
    for (int i = tid; i < N_BANDS * N_END / 4; i += 256)
        ((float4*)Ds)[i] = ((const float4*)D)[i];
    for (int i = tid; i < 1024 / 4; i += 256) {
        ((float4*)Dhi)[i] = ((const float4*)g_DeltaHi)[i];
        ((float4*)Dlo)[i] = ((const float4*)g_DeltaLo)[i];
    }
    if (tid < N_END) { gbh[tid] = g_gbarHi[tid]; gbl[tid] = g_gbarLo[tid]; }
    if (tid < N_BANDS) dbar_s[tid] = g_dbar[tid];
    if (tid < N_UNROLL) ets[tid] = etas[tid];
    __syncthreads();

    const int warp = tid >> 5, lane = tid & 31;
    float* xw = stage + warp * 1056;          // 32 x 33
    const int cb = warp * 512 + lane;         // + q*32
    const int p0 = (blockIdx.x * 8 + warp) * 32;

    // ==== Pass A: init logits = x@D fp32, ktile8 round-robin 2-WAY ==========
    u64 c2[16];
    {
        u64 P0[16], P1[16];
        #pragma unroll
        for (int i = 0; i < 16; i++) { P0[i] = 0ull; P1[i] = 0ull; }
        for (int t = 0; t < 7; t++) {
            #pragma unroll
            for (int r = 0; r < 32; r++)
                xw[r * 33 + lane] = x[(size_t)(p0 + r) * N_BANDS + t * 32 + lane];
            __syncwarp();
            #pragma unroll
            for (int st = 0; st < 4; st++) {       // global ktile = 4t+st
                u64* P = (st & 1) ? P1 : P0;
                #pragma unroll
                for (int j = 0; j < 8; j++) {
                    const int bb = st * 8 + j;
                    const int b  = t * 32 + bb;
                    float xv = xw[lane * 33 + bb];
                    u64 xb2 = pack2(xv, xv);
                    const ulonglong2* dr = (const ulonglong2*)(Ds + b * 32);
                    #pragma unroll
                    for (int q = 0; q < 8; q++) {
                        ulonglong2 dv = dr[q];
                        P[2 * q]     = ffma2(xb2, dv.x, P[2 * q]);
                        P[2 * q + 1] = ffma2(xb2, dv.y, P[2 * q + 1]);
                    }
                }
            }
            __syncwarp();
        }
        #pragma unroll
        for (int i = 0; i < 16; i++) c2[i] = fadd2(P0[i], P1[i]);
    }

    // ==== alpha0 = softmax(fp32 logits): serial max/sum, div.rn =============
    float a[32];
    {
        float la[32];
        #pragma unroll
        for (int i = 0; i < 16; i++) unpack2(c2[i], la[2 * i], la[2 * i + 1]);
        float m = la[0];
        #pragma unroll
        for (int e = 1; e < 32; e++) m = fmaxf(m, la[e]);
        float w[32];
        #pragma unroll
        for (int e = 0; e < 32; e++) w[e] = myexpf(la[e] - m);
        float S = w[0];
        #pragma unroll
        for (int e = 1; e < 32; e++) S = S + w[e];
        #pragma unroll
        for (int e = 0; e < 32; e++) a[e] = fdiv_rn(w[e], S);
    }

    // ==== Pass B: c-hat = (x - dbar)@D, TwoProd+Kahan -> df in SMEM =========
    {
        u64 cs_[16], cc_[16], ce_[16];
        #pragma unroll
        for (int i = 0; i < 16; i++) { cs_[i] = 0ull; cc_[i] = 0ull; ce_[i] = 0ull; }
        for (int t = 0; t < 7; t++) {
            #pragma unroll
            for (int r = 0; r < 32; r++)
                xw[r * 33 + lane] = x[(size_t)(p0 + r) * N_BANDS + t * 32 + lane];
            __syncwarp();
            #pragma unroll 4
            for (int bb = 0; bb < 32; bb++) {
                const int b = t * 32 + bb;
                float xv = xw[lane * 33 + bb];
                float nd = -dbar_s[b];
                float sB = xv + nd;
                float zB = sB - xv;
                float eB = (xv - (sB - zB)) + (nd - zB);
                u64 s2 = pack2(sB, sB);
                u64 e2 = pack2(eB, eB);
                const ulonglong2* dr = (const ulonglong2*)(Ds + b * 32);
                #pragma unroll
                for (int q = 0; q < 8; q++) {
                    ulonglong2 dv = dr[q];
                    kah_tp(s2, dv.x, e2, dv.x, cs_[2 * q],     cc_[2 * q],     ce_[2 * q]);
                    kah_tp(s2, dv.y, e2, dv.y, cs_[2 * q + 1], cc_[2 * q + 1], ce_[2 * q + 1]);
                }
            }
            __syncwarp();
        }
        #pragma unroll
        for (int q = 0; q < 16; q++) {
            u64 lo = fsub2(ce_[q], cc_[q]);
            u64 hi = fadd2(cs_[q], lo);
            u64 z  = fsub2(hi, cs_[q]);
            u64 l2 = fadd2(fsub2(cs_[q], fsub2(hi, z)), fsub2(lo, z));
            cHI[cb + q * 32] = hi;
            cLO[cb + q * 32] = l2;
        }
    }

    // ==== 12 iterations: PLAIN dual (hi,lo) FFMA matvecs =====================
    for (int it = 0; it < N_UNROLL; it++) {
        const float eta = ets[it];
        const u64 eta2 = pack2(eta, eta);

        u64 th[16], tl[16];
        #pragma unroll
        for (int i = 0; i < 16; i++) { th[i] = 0ull; tl[i] = 0ull; }
        #pragma unroll 4
        for (int k = 0; k < 32; k++) {
            u64 ak2 = pack2(a[k], a[k]);
            const ulonglong2* dh = (const ulonglong2*)(Dhi + k * 32);
            const ulonglong2* dl = (const ulonglong2*)(Dlo + k * 32);
            #pragma unroll
            for (int q = 0; q < 8; q++) {
                ulonglong2 hv = dh[q];
                ulonglong2 lv = dl[q];
                th[2 * q]     = ffma2(ak2, hv.x, th[2 * q]);
                th[2 * q + 1] = ffma2(ak2, hv.y, th[2 * q + 1]);
                tl[2 * q]     = ffma2(ak2, lv.x, tl[2 * q]);
                tl[2 * q + 1] = ffma2(ak2, lv.y, tl[2 * q + 1]);
            }
        }

        // b_hi = eta*(chi - th), b_lo = eta*(clo - tl)
        float bhf[32], blf[32];
        #pragma unroll
        for (int q = 0; q < 16; q++) {
            u64 h = fmul2(eta2, fsub2(cHI[cb + q * 32], th[q]));
            u64 l = fmul2(eta2, fsub2(cLO[cb + q * 32], tl[q]));
            unpack2(h, bhf[2 * q], bhf[2 * q + 1]);
            unpack2(l, blf[2 * q], blf[2 * q + 1]);
        }

        float m = bhf[0];
        #pragma unroll
        for (int e = 1; e < 32; e++) m = fmaxf(m, bhf[e]);
        float S = 0.f;
        float w[32];
        #pragma unroll
        for (int e = 0; e < 32; e++) {
            float nm = -m;
            float s1 = bhf[e] + nm;
            float z1 = s1 - bhf[e];
            float e1 = (bhf[e] - (s1 - z1)) + (nm - z1);
            float al = e1 + blf[e];
            float E  = myexpf(s1);
            E = fmaf(E, al, E);
            float wv = a[e] * E;
            w[e] = wv;
            S = S + wv;
        }
        #pragma unroll
        for (int e = 0; e < 32; e++) a[e] = fdiv_rn(w[e], S);
    }

    // ==== outputs =============================================================
    #pragma unroll
    for (int e = 0; e < 32; e++) xw[lane * 33 + e] = a[e];
    __syncwarp();
    #pragma unroll
    for (int r = 0; r < 32; r++)
        alpha_out[(size_t)(p0 + r) * N_END + lane] = xw[r * 33 + lane];
    __syncwarp();

    {
        u64 ap2[16];
        #pragma unroll
        for (int i = 0; i < 16; i++) ap2[i] = pack2(a[2 * i], a[2 * i + 1]);
        for (int t = 0; t < 7; t++) {
            #pragma unroll 4
            for (int bb = 0; bb < 32; bb++) {
                const int b = t * 32 + bb;
                const ulonglong2* dr = (const ulonglong2*)(Ds + b * 32);
                u64 ac0 = 0ull, ac1 = 0ull;
                #pragma unroll
                for (int q = 0; q < 8; q++) {
                    ulonglong2 dv = dr[q];
                    ac0 = ffma2(ap2[2 * q],     dv.x, ac0);
                    ac1 = ffma2(ap2[2 * q + 1], dv.y, ac1);
                }
                u64 ss = fadd2(ac0, ac1);
                float h0, h1; unpack2(ss, h0, h1);
                xw[lane * 33 + bb] = h0 + h1;
            }
            __syncwarp();
            #pragma unroll
            for (int r = 0; r < 32; r++)
                xhat[(size_t)(p0 + r) * N_BANDS + t * 32 + lane] = xw[r * 33 + lane];
            __syncwarp();
        }
    }
}

extern "C" void kernel_launch(void* const* d_in, const int* in_sizes, int n_in,
                              void* d_out, int out_size) {
    const float* x    = (const float*)d_in[0];
    const float* D    = (const float*)d_in[1];
    const float* etas = (const float*)d_in[2];
    float* out   = (float*)d_out;
    float* xhat  = out;                                   // [N, 224]
    float* alpha = out + (size_t)N_PIXELS * N_BANDS;      // [N, 32]

    stats_kernel<<<1, 256>>>(D);
    delta_kernel<<<8, 128>>>(D);

    const int smem_bytes = 50736 * 4;                     // 202,944 B
    cudaFuncSetAttribute(eda_kernel,
                         cudaFuncAttributeMaxDynamicSharedMemorySize, smem_bytes);
    eda_kernel<<<N_PIXELS / 256, 256, smem_bytes>>>(x, D, etas, xhat, alpha);
}